// round 15
// baseline (speedup 1.0000x reference)
#include <cuda_runtime.h>
#include <cuda_bf16.h>
#include <stdint.h>
#include <math.h>

// Problem constants (fixed by the reference's setup_inputs)
#define NG    12500
#define ROWS2 (2*NG)
#define HID   256

#define NCTA  296                            // 2 CTAs/SM x 148 SMs (<= capacity)

// Scratch (device globals; no allocation allowed)
__device__ __nv_bfloat16 g_bufA[ROWS2 * HID];
__device__ __nv_bfloat16 g_bufB[ROWS2 * HID];
__device__ __nv_bfloat16 g_bufC[NG * 512];
__device__ __nv_bfloat16 g_bufW[565248];     // bf16 W^T ([N][K]), concatenated

// Device-wide barrier state (epoch barrier; replay-safe: count self-resets,
// epoch compared relatively and monotonically increases across graph replays)
__device__ unsigned g_cnt = 0;
__device__ unsigned g_epoch = 0;

// Weight segment offsets (elements) in g_bufW
#define OFF_W2  0
#define OFF_W3  65536
#define OFF_WL1 131072
#define OFF_WL2 393216
#define OFF_WL3 524288
#define OFF_WL4 557056

// Phase tile counts
#define P1_TILES 879                         // 391 enc tiles + 488 cvt tiles
#define ENC_TILES 391
#define P2_TILES 522                         // conv3: 261 x 2
#define P3_TILES 524                         // Wl1: 131 x 4
#define P4_TILES 262                         // Wl2: 131 x 2
#define P5_TILES 196                         // fused34: 64-row tiles

// ---------------------------------------------------------------------------
// Helpers
// ---------------------------------------------------------------------------
__device__ __forceinline__ uint32_t smem_u32(const void* p) {
    uint32_t a;
    asm("{ .reg .u64 t; cvta.to.shared.u64 t, %1; cvt.u32.u64 %0, t; }" : "=r"(a) : "l"(p));
    return a;
}
__device__ __forceinline__ float fast_sigmoid(float x) {
    return __fdividef(1.0f, 1.0f + __expf(-x));
}
#define CP_ASYNC16(dst, src) \
    asm volatile("cp.async.cg.shared.global [%0], [%1], 16;" :: "r"(dst), "l"(src))
#define CP_COMMIT() asm volatile("cp.async.commit_group;" ::: "memory")
#define CP_WAIT1()  asm volatile("cp.async.wait_group 1;" ::: "memory")
#define CP_WAIT0()  asm volatile("cp.async.wait_group 0;" ::: "memory")

__device__ __forceinline__ void ldmx4(uint32_t* r, uint32_t addr) {
    asm volatile("ldmatrix.sync.aligned.m8n8.x4.shared.b16 {%0,%1,%2,%3}, [%4];"
        : "=r"(r[0]), "=r"(r[1]), "=r"(r[2]), "=r"(r[3]) : "r"(addr));
}
__device__ __forceinline__ void mma16(float* c, const uint32_t* a, const uint32_t* b) {
    asm volatile(
        "mma.sync.aligned.m16n8k16.row.col.f32.bf16.bf16.f32 "
        "{%0,%1,%2,%3}, {%4,%5,%6,%7}, {%8,%9}, {%0,%1,%2,%3};"
        : "+f"(c[0]), "+f"(c[1]), "+f"(c[2]), "+f"(c[3])
        : "r"(a[0]), "r"(a[1]), "r"(a[2]), "r"(a[3]), "r"(b[0]), "r"(b[1]));
}

// Device-wide barrier (all NCTA CTAs must be resident — guaranteed by
// launch_bounds(256,2) + SMEM fitting 2 CTAs/SM and grid == 2*148).
__device__ __forceinline__ void grid_bar() {
    __syncthreads();
    if (threadIdx.x == 0) {
        __threadfence();
        unsigned e = *((volatile unsigned*)&g_epoch);
        if (atomicAdd(&g_cnt, 1u) == (unsigned)(NCTA - 1)) {
            g_cnt = 0;
            __threadfence();
            *((volatile unsigned*)&g_epoch) = e + 1u;
        } else {
            while (*((volatile unsigned*)&g_epoch) == e) { __nanosleep(64); }
        }
        __threadfence();
    }
    __syncthreads();
}

// ---------------------------------------------------------------------------
// Weight-segment transpose tile (32x32) into dynamic SMEM scratch.
// b: <64 W2 | <128 W3 | <384 Wl1 | <512 Wl2 | <544 Wl3 | else Wl4.
// ---------------------------------------------------------------------------
__device__ __forceinline__ void cvt_block(int b, float* ts,
                                          const float* W2, const float* W3,
                                          const float* Wl1, const float* Wl2,
                                          const float* Wl3, const float* Wl4,
                                          __nv_bfloat16* dst, int tid) {
    const float* src; int off, Kd, Nd, t;
    if      (b < 64)  { src = W2;  off = OFF_W2;  Kd = 256; Nd = 256; t = b; }
    else if (b < 128) { src = W3;  off = OFF_W3;  Kd = 256; Nd = 256; t = b - 64; }
    else if (b < 384) { src = Wl1; off = OFF_WL1; Kd = 512; Nd = 512; t = b - 128; }
    else if (b < 512) { src = Wl2; off = OFF_WL2; Kd = 512; Nd = 256; t = b - 384; }
    else if (b < 544) { src = Wl3; off = OFF_WL3; Kd = 256; Nd = 128; t = b - 512; }
    else              { src = Wl4; off = OFF_WL4; Kd = 128; Nd = 64;  t = b - 544; }
    const int ntn = Nd >> 5;
    const int tk = t / ntn, tn = t % ntn;
    const int r = tid >> 5, c = tid & 31;
    #pragma unroll
    for (int i = 0; i < 4; ++i) {
        int k = tk * 32 + r + i * 8;
        ts[(r + i * 8) * 33 + c] = src[(size_t)k * Nd + tn * 32 + c];
    }
    __syncthreads();
    #pragma unroll
    for (int i = 0; i < 4; ++i) {
        int n = tn * 32 + r + i * 8;
        dst[(size_t)off + (size_t)n * Kd + tk * 32 + c] = __float2bfloat16(ts[c * 33 + r + i * 8]);
    }
    __syncthreads();
}

// ===========================================================================
// Tile loaders
// ===========================================================================
#define AS_STRIDE 72
#define NSTAGE 3
#define BB_BYTES (128 * AS_STRIDE * 2)       // 18432

template<int MT>
__device__ __forceinline__ void load_tileM(uint32_t sbuf,
                                           const __nv_bfloat16* __restrict__ A,
                                           const __nv_bfloat16* __restrict__ Wt,
                                           int M, int K, int N, int m0, int n0, int k0, int tid) {
    constexpr int ABYTES = MT * 32 * AS_STRIDE * 2;
    #pragma unroll
    for (int i = 0; i < MT; ++i) {
        int idx = tid + 256 * i;
        int row = idx >> 3;
        int c8 = (idx & 7) * 8;
        int gr = m0 + row;
        if (gr >= M) gr = M - 1;
        CP_ASYNC16(sbuf + (uint32_t)(row * AS_STRIDE + c8) * 2, A + (size_t)gr * K + k0 + c8);
    }
    #pragma unroll
    for (int i = 0; i < 4; ++i) {
        int idx = tid + 256 * i;
        int row = idx >> 3;
        int c8 = (idx & 7) * 8;
        int gn = n0 + row;
        if (gn >= N) gn = 0;
        CP_ASYNC16(sbuf + ABYTES + (uint32_t)(row * AS_STRIDE + c8) * 2,
                   Wt + (size_t)gn * K + k0 + c8);
    }
}

__device__ __forceinline__ void load_tileB8(uint32_t sbuf,
                                            const __nv_bfloat16* __restrict__ Wt,
                                            int K, int k0, int tid) {
    #pragma unroll
    for (int i = 0; i < 8; ++i) {
        int idx = tid + 256 * i;
        int row = idx >> 3;
        int c8 = (idx & 7) * 8;
        CP_ASYNC16(sbuf + (uint32_t)(row * AS_STRIDE + c8) * 2,
                   Wt + (size_t)row * K + k0 + c8);
    }
}

// ===========================================================================
// GEMM tile (MT=3, relu epilogue, optional split-concat), 3-stage pipeline.
// ===========================================================================
__device__ void gemm_tile3(const __nv_bfloat16* __restrict__ A,
                           const __nv_bfloat16* __restrict__ Wt,
                           const float* __restrict__ bias,
                           __nv_bfloat16* __restrict__ Cout,
                           int M, int K, int N, int ldc, int mhalf, bool split,
                           int m0, int n0, uint32_t sb, int tid) {
    constexpr int ABYTES = 3 * 32 * AS_STRIDE * 2;
    constexpr int BUFB = ABYTES + BB_BYTES;
    const int lane = tid & 31;
    const int wid = tid >> 5;
    const int wm = wid & 1;
    const int wn = wid >> 1;
    const int nChunks = K >> 6;

    float acc[3][4][4];
    #pragma unroll
    for (int mt = 0; mt < 3; ++mt)
        #pragma unroll
        for (int nt = 0; nt < 4; ++nt)
            #pragma unroll
            for (int q = 0; q < 4; ++q) acc[mt][nt][q] = 0.0f;

    const uint32_t aOff = (uint32_t)((wm * 48 + (lane & 15)) * AS_STRIDE + (lane >> 4) * 8) * 2;
    const uint32_t bOff = (uint32_t)((wn * 32 + (lane >> 4) * 8 + (lane & 7)) * AS_STRIDE
                                     + ((lane >> 3) & 1) * 8) * 2;

    load_tileM<3>(sb, A, Wt, M, K, N, m0, n0, 0, tid);
    CP_COMMIT();
    load_tileM<3>(sb + BUFB, A, Wt, M, K, N, m0, n0, 64, tid);
    CP_COMMIT();

    for (int ch = 0; ch < nChunks; ++ch) {
        CP_WAIT1();
        __syncthreads();
        const int pf = ch + NSTAGE - 1;
        if (pf < nChunks)
            load_tileM<3>(sb + (uint32_t)(pf % NSTAGE) * BUFB, A, Wt, M, K, N,
                          m0, n0, pf << 6, tid);
        CP_COMMIT();

        const uint32_t bufA = sb + (uint32_t)(ch % NSTAGE) * BUFB;
        const uint32_t bufB = bufA + ABYTES;
        #pragma unroll
        for (int ks = 0; ks < 4; ++ks) {
            const uint32_t kb = (uint32_t)(ks * 16) * 2;
            uint32_t afr[3][4];
            #pragma unroll
            for (int mt = 0; mt < 3; ++mt)
                ldmx4(afr[mt], bufA + aOff + (uint32_t)(mt * 16 * AS_STRIDE) * 2 + kb);
            uint32_t bfr[4][2];
            #pragma unroll
            for (int p = 0; p < 2; ++p) {
                uint32_t r[4];
                ldmx4(r, bufB + bOff + (uint32_t)(p * 16 * AS_STRIDE) * 2 + kb);
                bfr[2 * p][0] = r[0]; bfr[2 * p][1] = r[1];
                bfr[2 * p + 1][0] = r[2]; bfr[2 * p + 1][1] = r[3];
            }
            #pragma unroll
            for (int mt = 0; mt < 3; ++mt)
                #pragma unroll
                for (int nt = 0; nt < 4; ++nt)
                    mma16(acc[mt][nt], afr[mt], bfr[nt]);
        }
    }

    const int lg = lane >> 2;
    const int lt = lane & 3;
    #pragma unroll
    for (int mt = 0; mt < 3; ++mt) {
        #pragma unroll
        for (int nt = 0; nt < 4; ++nt) {
            const int gc = n0 + wn * 32 + nt * 8 + 2 * lt;
            if (gc >= N) continue;
            const float b0 = bias[gc], b1v = bias[gc + 1];
            #pragma unroll
            for (int h = 0; h < 2; ++h) {
                const int gr = m0 + wm * 48 + mt * 16 + lg + 8 * h;
                if (gr >= M) continue;
                float v0 = acc[mt][nt][2 * h + 0] + b0;
                float v1 = acc[mt][nt][2 * h + 1] + b1v;
                size_t base;
                if (split) base = (gr < mhalf) ? ((size_t)gr * ldc + gc)
                                               : ((size_t)(gr - mhalf) * ldc + 256 + gc);
                else       base = (size_t)gr * ldc + gc;
                __nv_bfloat162 o;
                o.x = __float2bfloat16(fmaxf(v0, 0.0f));
                o.y = __float2bfloat16(fmaxf(v1, 0.0f));
                *reinterpret_cast<__nv_bfloat162*>(Cout + base) = o;
            }
        }
    }
    __syncthreads();                         // SMEM reuse across tile-loop iterations
}

// ===========================================================================
// Encoder layer1+conv2 fused tile (full-width 64 x 256).
// ===========================================================================
#define AR_ST 264
#define AR_BYTES (64 * AR_ST * 2)            // 33792
#define EB_BYTES (256 * AS_STRIDE * 2)       // 36864
#define E1_SMEM (AR_BYTES + 2 * EB_BYTES)    // 107520  (mega kernel SMEM size)

__device__ void enc1_tile(int m0,
                          const float* __restrict__ x1, const float* __restrict__ x2,
                          const float* __restrict__ W1, const float* __restrict__ b1,
                          const __nv_bfloat16* __restrict__ W2t, const float* __restrict__ b2,
                          __nv_bfloat16* __restrict__ Cout,
                          char* smem, float (*sx)[4], uint32_t sb, int tid) {
    const int lane = tid & 31;
    const int wid = tid >> 5;
    const int wm = wid & 1;
    const int wn = wid >> 1;
    const int M = ROWS2, K = 256;

    load_tileB8(sb + AR_BYTES, W2t, K, 0, tid);
    CP_COMMIT();

    if (tid < 64) {
        int gr = m0 + tid;
        if (gr >= M) gr = M - 1;
        const float* p = (gr < NG) ? (x1 + (size_t)gr * 12) : (x2 + (size_t)(gr - NG) * 12);
        sx[tid][0] = 0.25f * (p[0] + p[3] + p[6] + p[9]);
        sx[tid][1] = 0.25f * (p[1] + p[4] + p[7] + p[10]);
        sx[tid][2] = 0.25f * (p[2] + p[5] + p[8] + p[11]);
    }
    __syncthreads();

    {
        const float w0 = W1[tid], w1 = W1[256 + tid], w2 = W1[512 + tid], bb = b1[tid];
        #pragma unroll 4
        for (int r = 0; r < 64; ++r) {
            float v = fmaf(sx[r][0], w0, fmaf(sx[r][1], w1, fmaf(sx[r][2], w2, bb)));
            *reinterpret_cast<__nv_bfloat16*>(smem + (uint32_t)(r * AR_ST + tid) * 2) =
                __float2bfloat16(fmaxf(v, 0.0f));
        }
    }

    float acc[2][8][4];
    #pragma unroll
    for (int mt = 0; mt < 2; ++mt)
        #pragma unroll
        for (int nt = 0; nt < 8; ++nt)
            #pragma unroll
            for (int q = 0; q < 4; ++q) acc[mt][nt][q] = 0.0f;

    const uint32_t aOff = (uint32_t)((wm * 32 + (lane & 15)) * AR_ST + (lane >> 4) * 8) * 2;
    const uint32_t bOff = (uint32_t)((wn * 64 + (lane >> 4) * 8 + (lane & 7)) * AS_STRIDE
                                     + ((lane >> 3) & 1) * 8) * 2;

    for (int ch = 0; ch < 4; ++ch) {
        if (ch + 1 < 4)
            load_tileB8(sb + AR_BYTES + (uint32_t)((ch + 1) & 1) * EB_BYTES, W2t, K,
                        (ch + 1) << 6, tid);
        CP_COMMIT();
        CP_WAIT1();
        __syncthreads();

        const uint32_t bufB = sb + AR_BYTES + (uint32_t)(ch & 1) * EB_BYTES;
        #pragma unroll
        for (int ks = 0; ks < 4; ++ks) {
            const uint32_t kbA = (uint32_t)(ch * 64 + ks * 16) * 2;
            const uint32_t kbB = (uint32_t)(ks * 16) * 2;
            uint32_t afr[2][4];
            #pragma unroll
            for (int mt = 0; mt < 2; ++mt)
                ldmx4(afr[mt], sb + aOff + (uint32_t)(mt * 16 * AR_ST) * 2 + kbA);
            uint32_t bfr[8][2];
            #pragma unroll
            for (int p = 0; p < 4; ++p) {
                uint32_t r[4];
                ldmx4(r, bufB + bOff + (uint32_t)(p * 16 * AS_STRIDE) * 2 + kbB);
                bfr[2 * p][0] = r[0]; bfr[2 * p][1] = r[1];
                bfr[2 * p + 1][0] = r[2]; bfr[2 * p + 1][1] = r[3];
            }
            #pragma unroll
            for (int mt = 0; mt < 2; ++mt)
                #pragma unroll
                for (int nt = 0; nt < 8; ++nt)
                    mma16(acc[mt][nt], afr[mt], bfr[nt]);
        }
        __syncthreads();
    }

    const int lg = lane >> 2;
    const int lt = lane & 3;
    #pragma unroll
    for (int mt = 0; mt < 2; ++mt) {
        #pragma unroll
        for (int nt = 0; nt < 8; ++nt) {
            const int gc = wn * 64 + nt * 8 + 2 * lt;
            const float b0 = b2[gc], b1v = b2[gc + 1];
            #pragma unroll
            for (int h = 0; h < 2; ++h) {
                const int gr = m0 + wm * 32 + mt * 16 + lg + 8 * h;
                if (gr >= M) continue;
                __nv_bfloat162 o;
                o.x = __float2bfloat16(fmaxf(acc[mt][nt][2 * h + 0] + b0, 0.0f));
                o.y = __float2bfloat16(fmaxf(acc[mt][nt][2 * h + 1] + b1v, 0.0f));
                *reinterpret_cast<__nv_bfloat162*>(Cout + (size_t)gr * 256 + gc) = o;
            }
        }
    }
    __syncthreads();
}

// ===========================================================================
// Fused Wl3+Wl4 tile (64 rows, 2-stage), fast sigmoid epilogue.
// ===========================================================================
#define L3_STRIDE 136
#define F2_BUF ((64 + 128) * AS_STRIDE * 2)  // 27648
#define F2_PIPE (2 * F2_BUF)                 // 55296
#define L3BYTES (64 * L3_STRIDE * 2)         // 17408

__device__ void fused_tile(int m0,
                           const __nv_bfloat16* __restrict__ A,
                           const __nv_bfloat16* __restrict__ W3t,
                           const __nv_bfloat16* __restrict__ W4t,
                           const float* __restrict__ b3, const float* __restrict__ b4,
                           float* __restrict__ out, int M,
                           char* smem, uint32_t sb, int tid) {
    const uint32_t l3b = sb + F2_PIPE;
    const uint32_t w4b = l3b + L3BYTES;
    const int lane = tid & 31;
    const int wid = tid >> 5;
    const int wm = wid & 1;
    const int wn = wid >> 1;

    #pragma unroll
    for (int i = 0; i < 4; ++i) {
        int idx = tid + 256 * i;
        int row = idx >> 4;
        int c8 = (idx & 15) * 8;
        CP_ASYNC16(w4b + (uint32_t)(row * L3_STRIDE + c8) * 2, W4t + row * 128 + c8);
    }
    CP_COMMIT();

    float acc[2][4][4];
    #pragma unroll
    for (int mt = 0; mt < 2; ++mt)
        #pragma unroll
        for (int nt = 0; nt < 4; ++nt)
            #pragma unroll
            for (int q = 0; q < 4; ++q) acc[mt][nt][q] = 0.0f;

    const uint32_t aOff = (uint32_t)((wm * 32 + (lane & 15)) * AS_STRIDE + (lane >> 4) * 8) * 2;
    const uint32_t bOff = (uint32_t)((wn * 32 + (lane >> 4) * 8 + (lane & 7)) * AS_STRIDE
                                     + ((lane >> 3) & 1) * 8) * 2;

    load_tileM<2>(sb, A, W3t, M, 256, 128, m0, 0, 0, tid);
    CP_COMMIT();
    for (int ch = 0; ch < 4; ++ch) {
        if (ch + 1 < 4)
            load_tileM<2>(sb + (uint32_t)((ch + 1) & 1) * F2_BUF, A, W3t, M, 256, 128,
                          m0, 0, (ch + 1) << 6, tid);
        CP_COMMIT();
        CP_WAIT1();
        __syncthreads();
        const uint32_t bufA = sb + (uint32_t)(ch & 1) * F2_BUF;
        const uint32_t bufB = bufA + 64 * AS_STRIDE * 2;
        #pragma unroll
        for (int ks = 0; ks < 4; ++ks) {
            const uint32_t kb = (uint32_t)(ks * 16) * 2;
            uint32_t afr[2][4];
            #pragma unroll
            for (int mt = 0; mt < 2; ++mt)
                ldmx4(afr[mt], bufA + aOff + (uint32_t)(mt * 16 * AS_STRIDE) * 2 + kb);
            uint32_t bfr[4][2];
            #pragma unroll
            for (int p = 0; p < 2; ++p) {
                uint32_t r[4];
                ldmx4(r, bufB + bOff + (uint32_t)(p * 16 * AS_STRIDE) * 2 + kb);
                bfr[2 * p][0] = r[0]; bfr[2 * p][1] = r[1];
                bfr[2 * p + 1][0] = r[2]; bfr[2 * p + 1][1] = r[3];
            }
            #pragma unroll
            for (int mt = 0; mt < 2; ++mt)
                #pragma unroll
                for (int nt = 0; nt < 4; ++nt)
                    mma16(acc[mt][nt], afr[mt], bfr[nt]);
        }
        __syncthreads();
    }

    const int lg = lane >> 2;
    const int lt = lane & 3;
    #pragma unroll
    for (int mt = 0; mt < 2; ++mt) {
        #pragma unroll
        for (int nt = 0; nt < 4; ++nt) {
            const int gc = wn * 32 + nt * 8 + 2 * lt;
            const float b0 = b3[gc], b1v = b3[gc + 1];
            #pragma unroll
            for (int h = 0; h < 2; ++h) {
                const int row = wm * 32 + mt * 16 + lg + 8 * h;
                __nv_bfloat162 o;
                o.x = __float2bfloat16(fmaxf(acc[mt][nt][2 * h + 0] + b0, 0.0f));
                o.y = __float2bfloat16(fmaxf(acc[mt][nt][2 * h + 1] + b1v, 0.0f));
                *reinterpret_cast<__nv_bfloat162*>(smem + F2_PIPE + (uint32_t)(row * L3_STRIDE + gc) * 2) = o;
            }
        }
    }
    CP_WAIT0();
    __syncthreads();

    float acc2[2][2][4];
    #pragma unroll
    for (int mt = 0; mt < 2; ++mt)
        #pragma unroll
        for (int nt = 0; nt < 2; ++nt)
            #pragma unroll
            for (int q = 0; q < 4; ++q) acc2[mt][nt][q] = 0.0f;

    const uint32_t aOff2 = (uint32_t)((wm * 32 + (lane & 15)) * L3_STRIDE + (lane >> 4) * 8) * 2;
    const uint32_t bOff2 = (uint32_t)((wn * 16 + (lane >> 4) * 8 + (lane & 7)) * L3_STRIDE
                                      + ((lane >> 3) & 1) * 8) * 2;
    #pragma unroll
    for (int ks = 0; ks < 8; ++ks) {
        const uint32_t kb = (uint32_t)(ks * 16) * 2;
        uint32_t afr[2][4];
        #pragma unroll
        for (int mt = 0; mt < 2; ++mt)
            ldmx4(afr[mt], l3b + aOff2 + (uint32_t)(mt * 16 * L3_STRIDE) * 2 + kb);
        uint32_t r[4];
        ldmx4(r, w4b + bOff2 + kb);
        uint32_t bfr[2][2] = {{r[0], r[1]}, {r[2], r[3]}};
        #pragma unroll
        for (int mt = 0; mt < 2; ++mt)
            #pragma unroll
            for (int nt = 0; nt < 2; ++nt)
                mma16(acc2[mt][nt], afr[mt], bfr[nt]);
    }

    #pragma unroll
    for (int mt = 0; mt < 2; ++mt) {
        #pragma unroll
        for (int nt = 0; nt < 2; ++nt) {
            const int gc = wn * 16 + nt * 8 + 2 * lt;
            const float b0 = b4[gc], b1v = b4[gc + 1];
            #pragma unroll
            for (int h = 0; h < 2; ++h) {
                const int gr = m0 + wm * 32 + mt * 16 + lg + 8 * h;
                if (gr >= M) continue;
                float v0 = fast_sigmoid(acc2[mt][nt][2 * h + 0] + b0);
                float v1 = fast_sigmoid(acc2[mt][nt][2 * h + 1] + b1v);
                *reinterpret_cast<float2*>(out + (size_t)gr * 64 + gc) = make_float2(v0, v1);
            }
        }
    }
    __syncthreads();
}

// ===========================================================================
// Mega persistent kernel: all phases, device-wide barriers between them.
// ===========================================================================
__global__ __launch_bounds__(256, 2)
void mega(const float* __restrict__ x1, const float* __restrict__ x2,
          const float* __restrict__ W1, const float* __restrict__ b1,
          const float* __restrict__ W2, const float* __restrict__ b2,
          const float* __restrict__ W3, const float* __restrict__ b3,
          const float* __restrict__ Wl1, const float* __restrict__ bl1,
          const float* __restrict__ Wl2, const float* __restrict__ bl2,
          const float* __restrict__ Wl3, const float* __restrict__ bl3,
          const float* __restrict__ Wl4, const float* __restrict__ bl4,
          __nv_bfloat16* __restrict__ bufA, __nv_bfloat16* __restrict__ bufB,
          __nv_bfloat16* __restrict__ bufC, __nv_bfloat16* __restrict__ bufW,
          float* __restrict__ out) {
    extern __shared__ __align__(16) char smem[];
    __shared__ float sx[64][4];
    const int cta = blockIdx.x;
    const int tid = threadIdx.x;
    const uint32_t sb = smem_u32(smem);

    // Phase 0: convert W2 (64 tiles)
    for (int t = cta; t < 64; t += NCTA)
        cvt_block(t, reinterpret_cast<float*>(smem), W2, W3, Wl1, Wl2, Wl3, Wl4, bufW, tid);
    grid_bar();

    // Phase 1: enc1 (391 tiles) + convert W3..Wl4 (488 tiles)
    for (int t = cta; t < P1_TILES; t += NCTA) {
        if (t < ENC_TILES)
            enc1_tile(t * 64, x1, x2, W1, b1, bufW + OFF_W2, b2, bufB, smem, sx, sb, tid);
        else
            cvt_block(64 + (t - ENC_TILES), reinterpret_cast<float*>(smem),
                      W2, W3, Wl1, Wl2, Wl3, Wl4, bufW, tid);
    }
    grid_bar();

    // Phase 2: conv3 (split-concat write into bufC[NG,512])
    for (int t = cta; t < P2_TILES; t += NCTA)
        gemm_tile3(bufB, bufW + OFF_W3, b3, bufC, ROWS2, 256, 256, 512, NG, true,
                   (t >> 1) * 96, (t & 1) * 128, sb, tid);
    grid_bar();

    // Phase 3: Wl1 [NG,512]x[512,512]
    for (int t = cta; t < P3_TILES; t += NCTA)
        gemm_tile3(bufC, bufW + OFF_WL1, bl1, bufA, NG, 512, 512, 512, 0, false,
                   (t >> 2) * 96, (t & 3) * 128, sb, tid);
    grid_bar();

    // Phase 4: Wl2 [NG,512]x[512,256]
    for (int t = cta; t < P4_TILES; t += NCTA)
        gemm_tile3(bufA, bufW + OFF_WL2, bl2, bufB, NG, 512, 256, 256, 0, false,
                   (t >> 1) * 96, (t & 1) * 128, sb, tid);
    grid_bar();

    // Phase 5: fused Wl3+Wl4 -> sigmoid -> out
    for (int t = cta; t < P5_TILES; t += NCTA)
        fused_tile(t * 64, bufB, bufW + OFF_WL3, bufW + OFF_WL4, bl3, bl4, out, NG,
                   smem, sb, tid);
}

// ---------------------------------------------------------------------------
// Launch
// ---------------------------------------------------------------------------
extern "C" void kernel_launch(void* const* d_in, const int* in_sizes, int n_in,
                              void* d_out, int out_size) {
    const float* x1  = (const float*)d_in[0];
    const float* x2  = (const float*)d_in[3];
    const float* W1  = (const float*)d_in[6];
    const float* b1  = (const float*)d_in[7];
    const float* W2  = (const float*)d_in[8];
    const float* b2  = (const float*)d_in[9];
    const float* W3  = (const float*)d_in[10];
    const float* b3  = (const float*)d_in[11];
    const float* Wl1 = (const float*)d_in[12];
    const float* bl1 = (const float*)d_in[13];
    const float* Wl2 = (const float*)d_in[14];
    const float* bl2 = (const float*)d_in[15];
    const float* Wl3 = (const float*)d_in[16];
    const float* bl3 = (const float*)d_in[17];
    const float* Wl4 = (const float*)d_in[18];
    const float* bl4 = (const float*)d_in[19];
    float* out = (float*)d_out;

    __nv_bfloat16 *bufA, *bufB, *bufC, *bufW;
    cudaGetSymbolAddress((void**)&bufA, g_bufA);
    cudaGetSymbolAddress((void**)&bufB, g_bufB);
    cudaGetSymbolAddress((void**)&bufC, g_bufC);
    cudaGetSymbolAddress((void**)&bufW, g_bufW);

    cudaFuncSetAttribute(mega, cudaFuncAttributeMaxDynamicSharedMemorySize, E1_SMEM);

    mega<<<NCTA, 256, E1_SMEM>>>(x1, x2, W1, b1, W2, b2, W3, b3,
                                 Wl1, bl1, Wl2, bl2, Wl3, bl3, Wl4, bl4,
                                 bufA, bufB, bufC, bufW, out);
}

// round 16
// speedup vs baseline: 1.0420x; 1.0420x over previous
#include <cuda_runtime.h>
#include <cuda_bf16.h>
#include <stdint.h>
#include <math.h>

// Problem constants (fixed by the reference's setup_inputs)
#define NG    12500
#define ROWS2 (2*NG)
#define HID   256

// Scratch (device globals; no allocation allowed)
__device__ __nv_bfloat16 g_bufA[ROWS2 * HID];   // also viewed as [NG,512]
__device__ __nv_bfloat16 g_bufB[ROWS2 * HID];
__device__ __nv_bfloat16 g_bufC[NG * 512];
__device__ __nv_bfloat16 g_bufW[565248];        // bf16 W^T ([N][K]), concatenated

// Weight segment offsets (elements) in g_bufW
#define OFF_W2  0
#define OFF_W3  65536
#define OFF_WL1 131072
#define OFF_WL2 393216
#define OFF_WL3 524288
#define OFF_WL4 557056
#define W_TOTAL 565248

#define ENC_TILES 391                        // (ROWS2+63)/64
#define CVT_TAIL 488                         // conversion blocks folded into enc1

// ---------------------------------------------------------------------------
// Helpers
// ---------------------------------------------------------------------------
__device__ __forceinline__ uint32_t smem_u32(const void* p) {
    uint32_t a;
    asm("{ .reg .u64 t; cvta.to.shared.u64 t, %1; cvt.u32.u64 %0, t; }" : "=r"(a) : "l"(p));
    return a;
}
__device__ __forceinline__ float fast_sigmoid(float x) {
    // MUFU ex2 + rcp.approx path, independent of harness fast-math flags.
    return __fdividef(1.0f, 1.0f + __expf(-x));
}
#define CP_ASYNC16(dst, src) \
    asm volatile("cp.async.cg.shared.global [%0], [%1], 16;" :: "r"(dst), "l"(src))
#define CP_COMMIT() asm volatile("cp.async.commit_group;" ::: "memory")
#define CP_WAIT1()  asm volatile("cp.async.wait_group 1;" ::: "memory")
#define CP_WAIT0()  asm volatile("cp.async.wait_group 0;" ::: "memory")

__device__ __forceinline__ void ldmx4(uint32_t* r, uint32_t addr) {
    asm volatile("ldmatrix.sync.aligned.m8n8.x4.shared.b16 {%0,%1,%2,%3}, [%4];"
        : "=r"(r[0]), "=r"(r[1]), "=r"(r[2]), "=r"(r[3]) : "r"(addr));
}
__device__ __forceinline__ void mma16(float* c, const uint32_t* a, const uint32_t* b) {
    asm volatile(
        "mma.sync.aligned.m16n8k16.row.col.f32.bf16.bf16.f32 "
        "{%0,%1,%2,%3}, {%4,%5,%6,%7}, {%8,%9}, {%0,%1,%2,%3};"
        : "+f"(c[0]), "+f"(c[1]), "+f"(c[2]), "+f"(c[3])
        : "r"(a[0]), "r"(a[1]), "r"(a[2]), "r"(a[3]), "r"(b[0]), "r"(b[1]));
}

// ---------------------------------------------------------------------------
// Weight-segment transpose body (32x32 tile), b = global tile-block index.
// Mapping: b<64 W2 | <128 W3 | <384 Wl1 | <512 Wl2 | <544 Wl3 | else Wl4.
// ---------------------------------------------------------------------------
__device__ __forceinline__ void cvt_block(int b, float* ts /* [32][33] */,
                                          const float* W2, const float* W3,
                                          const float* Wl1, const float* Wl2,
                                          const float* Wl3, const float* Wl4,
                                          __nv_bfloat16* dst, int tid) {
    const float* src; int off, Kd, Nd, t;
    if      (b < 64)  { src = W2;  off = OFF_W2;  Kd = 256; Nd = 256; t = b; }
    else if (b < 128) { src = W3;  off = OFF_W3;  Kd = 256; Nd = 256; t = b - 64; }
    else if (b < 384) { src = Wl1; off = OFF_WL1; Kd = 512; Nd = 512; t = b - 128; }
    else if (b < 512) { src = Wl2; off = OFF_WL2; Kd = 512; Nd = 256; t = b - 384; }
    else if (b < 544) { src = Wl3; off = OFF_WL3; Kd = 256; Nd = 128; t = b - 512; }
    else              { src = Wl4; off = OFF_WL4; Kd = 128; Nd = 64;  t = b - 544; }
    const int ntn = Nd >> 5;
    const int tk = t / ntn, tn = t % ntn;
    const int r = tid >> 5, c = tid & 31;
    #pragma unroll
    for (int i = 0; i < 4; ++i) {
        int k = tk * 32 + r + i * 8;
        ts[(r + i * 8) * 33 + c] = src[(size_t)k * Nd + tn * 32 + c];
    }
    __syncthreads();
    #pragma unroll
    for (int i = 0; i < 4; ++i) {
        int n = tn * 32 + r + i * 8;
        dst[(size_t)off + (size_t)n * Kd + tk * 32 + c] = __float2bfloat16(ts[c * 33 + r + i * 8]);
    }
}

// Standalone: converts W2 only (64 blocks) — needed before enc1's GEMM.
__global__ __launch_bounds__(256)
void cvt_w2(const float* __restrict__ W2, __nv_bfloat16* __restrict__ dst) {
    __shared__ float ts[32 * 33];
    cvt_block(blockIdx.x, ts, W2, W2, W2, W2, W2, W2, dst, threadIdx.x);
}

// ===========================================================================
// Shared tile loaders
// ===========================================================================
#define AS_STRIDE 72                        // bf16 per smem row (64 + 8 pad) = 144B
#define NSTAGE 3
#define BB_BYTES (128 * AS_STRIDE * 2)      // 18432 (B tile: 128 n-rows)

template<int MT>
__device__ __forceinline__ void load_tileM(uint32_t sbuf,
                                           const __nv_bfloat16* __restrict__ A,
                                           const __nv_bfloat16* __restrict__ Wt,
                                           int M, int K, int N, int m0, int n0, int k0, int tid) {
    constexpr int ABYTES = MT * 32 * AS_STRIDE * 2;
    #pragma unroll
    for (int i = 0; i < MT; ++i) {           // A: MT*32 rows x 64 bf16
        int idx = tid + 256 * i;
        int row = idx >> 3;
        int c8 = (idx & 7) * 8;
        int gr = m0 + row;
        if (gr >= M) gr = M - 1;
        CP_ASYNC16(sbuf + (uint32_t)(row * AS_STRIDE + c8) * 2, A + (size_t)gr * K + k0 + c8);
    }
    #pragma unroll
    for (int i = 0; i < 4; ++i) {            // B: 128 n-rows x 64 bf16 of W^T
        int idx = tid + 256 * i;
        int row = idx >> 3;
        int c8 = (idx & 7) * 8;
        int gn = n0 + row;
        if (gn >= N) gn = 0;
        CP_ASYNC16(sbuf + ABYTES + (uint32_t)(row * AS_STRIDE + c8) * 2,
                   Wt + (size_t)gn * K + k0 + c8);
    }
}

// B-only loader, 256 n-rows (for enc1)
__device__ __forceinline__ void load_tileB8(uint32_t sbuf,
                                            const __nv_bfloat16* __restrict__ Wt,
                                            int K, int k0, int tid) {
    #pragma unroll
    for (int i = 0; i < 8; ++i) {
        int idx = tid + 256 * i;
        int row = idx >> 3;
        int c8 = (idx & 7) * 8;
        CP_ASYNC16(sbuf + (uint32_t)(row * AS_STRIDE + c8) * 2,
                   Wt + (size_t)row * K + k0 + c8);
    }
}

// ===========================================================================
// tc_gemm (R8-proven): MT*32 x 128 block, BK=64, 3-stage, 2 CTA/SM
// ===========================================================================
template<int MT, int EPI, bool SPLIT>
__global__ __launch_bounds__(256, 2)
void tc_gemm(const __nv_bfloat16* __restrict__ A, const __nv_bfloat16* __restrict__ Wt,
             const float* __restrict__ bias, void* __restrict__ Cout,
             int M, int K, int N, int ldc, int mhalf) {
    constexpr int ABYTES = MT * 32 * AS_STRIDE * 2;
    constexpr int BUFB = ABYTES + BB_BYTES;
    extern __shared__ __align__(16) char smem[];
    const uint32_t sb = smem_u32(smem);
    const int tid = threadIdx.x;
    const int lane = tid & 31;
    const int wid = tid >> 5;
    const int wm = wid & 1;
    const int wn = wid >> 1;
    const int m0 = blockIdx.x * (MT * 32);
    const int n0 = blockIdx.y * 128;
    const int nChunks = K >> 6;

    float acc[MT][4][4];
    #pragma unroll
    for (int mt = 0; mt < MT; ++mt)
        #pragma unroll
        for (int nt = 0; nt < 4; ++nt)
            #pragma unroll
            for (int q = 0; q < 4; ++q) acc[mt][nt][q] = 0.0f;

    const uint32_t aOff = (uint32_t)((wm * MT * 16 + (lane & 15)) * AS_STRIDE + (lane >> 4) * 8) * 2;
    const uint32_t bOff = (uint32_t)((wn * 32 + (lane >> 4) * 8 + (lane & 7)) * AS_STRIDE
                                     + ((lane >> 3) & 1) * 8) * 2;

    load_tileM<MT>(sb, A, Wt, M, K, N, m0, n0, 0, tid);
    CP_COMMIT();
    load_tileM<MT>(sb + BUFB, A, Wt, M, K, N, m0, n0, 64, tid);
    CP_COMMIT();

    for (int ch = 0; ch < nChunks; ++ch) {
        CP_WAIT1();
        __syncthreads();
        const int pf = ch + NSTAGE - 1;
        if (pf < nChunks)
            load_tileM<MT>(sb + (uint32_t)(pf % NSTAGE) * BUFB, A, Wt, M, K, N,
                           m0, n0, pf << 6, tid);
        CP_COMMIT();

        const uint32_t bufA = sb + (uint32_t)(ch % NSTAGE) * BUFB;
        const uint32_t bufB = bufA + ABYTES;
        #pragma unroll
        for (int ks = 0; ks < 4; ++ks) {
            const uint32_t kb = (uint32_t)(ks * 16) * 2;
            uint32_t afr[MT][4];
            #pragma unroll
            for (int mt = 0; mt < MT; ++mt)
                ldmx4(afr[mt], bufA + aOff + (uint32_t)(mt * 16 * AS_STRIDE) * 2 + kb);
            uint32_t bfr[4][2];
            #pragma unroll
            for (int p = 0; p < 2; ++p) {
                uint32_t r[4];
                ldmx4(r, bufB + bOff + (uint32_t)(p * 16 * AS_STRIDE) * 2 + kb);
                bfr[2 * p][0] = r[0]; bfr[2 * p][1] = r[1];
                bfr[2 * p + 1][0] = r[2]; bfr[2 * p + 1][1] = r[3];
            }
            #pragma unroll
            for (int mt = 0; mt < MT; ++mt)
                #pragma unroll
                for (int nt = 0; nt < 4; ++nt)
                    mma16(acc[mt][nt], afr[mt], bfr[nt]);
        }
    }

    const int lg = lane >> 2;
    const int lt = lane & 3;
    #pragma unroll
    for (int mt = 0; mt < MT; ++mt) {
        #pragma unroll
        for (int nt = 0; nt < 4; ++nt) {
            const int gc = n0 + wn * 32 + nt * 8 + 2 * lt;
            if (gc >= N) continue;
            const float b0 = bias[gc], b1v = bias[gc + 1];
            #pragma unroll
            for (int h = 0; h < 2; ++h) {
                const int gr = m0 + wm * MT * 16 + mt * 16 + lg + 8 * h;
                if (gr >= M) continue;
                float v0 = acc[mt][nt][2 * h + 0] + b0;
                float v1 = acc[mt][nt][2 * h + 1] + b1v;
                size_t base;
                if (SPLIT) base = (gr < mhalf) ? ((size_t)gr * ldc + gc)
                                               : ((size_t)(gr - mhalf) * ldc + 256 + gc);
                else       base = (size_t)gr * ldc + gc;
                if (EPI == 1) {
                    __nv_bfloat162 o;
                    o.x = __float2bfloat16(fmaxf(v0, 0.0f));
                    o.y = __float2bfloat16(fmaxf(v1, 0.0f));
                    *reinterpret_cast<__nv_bfloat162*>((__nv_bfloat16*)Cout + base) = o;
                } else {
                    v0 = fast_sigmoid(v0);
                    v1 = fast_sigmoid(v1);
                    *reinterpret_cast<float2*>((float*)Cout + base) = make_float2(v0, v1);
                }
            }
        }
    }
}

// ===========================================================================
// Encoder layer 1+2 fused, full-width (R11) + cvt tail blocks.
// ===========================================================================
#define AR_ST 264
#define AR_BYTES (64 * AR_ST * 2)             // 33792
#define EB_BYTES (256 * AS_STRIDE * 2)        // 36864
#define E1_SMEM (AR_BYTES + 2 * EB_BYTES)     // 107520

__global__ __launch_bounds__(256, 2)
void tc_enc1(const float* __restrict__ x1, const float* __restrict__ x2,
             const float* __restrict__ W1, const float* __restrict__ b1,
             const __nv_bfloat16* __restrict__ W2t, const float* __restrict__ b2,
             __nv_bfloat16* __restrict__ Cout,
             const float* __restrict__ W3f, const float* __restrict__ Wl1f,
             const float* __restrict__ Wl2f, const float* __restrict__ Wl3f,
             const float* __restrict__ Wl4f, __nv_bfloat16* __restrict__ dstW) {
    extern __shared__ __align__(16) char smem[];

    // --- cvt tail blocks: convert W3..Wl4 segments, then exit ---
    if (blockIdx.x >= ENC_TILES) {
        cvt_block(64 + (int)(blockIdx.x - ENC_TILES), reinterpret_cast<float*>(smem),
                  W3f, W3f, Wl1f, Wl2f, Wl3f, Wl4f, dstW, threadIdx.x);
        return;
    }

    __shared__ float sx[64][4];
    const uint32_t sb = smem_u32(smem);
    const int tid = threadIdx.x;
    const int lane = tid & 31;
    const int wid = tid >> 5;
    const int wm = wid & 1;
    const int wn = wid >> 1;
    const int m0 = blockIdx.x * 64;
    const int M = ROWS2, K = 256;

    load_tileB8(sb + AR_BYTES, W2t, K, 0, tid);
    CP_COMMIT();

    if (tid < 64) {
        int gr = m0 + tid;
        if (gr >= M) gr = M - 1;
        const float* p = (gr < NG) ? (x1 + (size_t)gr * 12) : (x2 + (size_t)(gr - NG) * 12);
        sx[tid][0] = 0.25f * (p[0] + p[3] + p[6] + p[9]);
        sx[tid][1] = 0.25f * (p[1] + p[4] + p[7] + p[10]);
        sx[tid][2] = 0.25f * (p[2] + p[5] + p[8] + p[11]);
    }
    __syncthreads();

    {
        const float w0 = W1[tid], w1 = W1[256 + tid], w2 = W1[512 + tid], bb = b1[tid];
        #pragma unroll 4
        for (int r = 0; r < 64; ++r) {
            float v = fmaf(sx[r][0], w0, fmaf(sx[r][1], w1, fmaf(sx[r][2], w2, bb)));
            *reinterpret_cast<__nv_bfloat16*>(smem + (uint32_t)(r * AR_ST + tid) * 2) =
                __float2bfloat16(fmaxf(v, 0.0f));
        }
    }

    float acc[2][8][4];
    #pragma unroll
    for (int mt = 0; mt < 2; ++mt)
        #pragma unroll
        for (int nt = 0; nt < 8; ++nt)
            #pragma unroll
            for (int q = 0; q < 4; ++q) acc[mt][nt][q] = 0.0f;

    const uint32_t aOff = (uint32_t)((wm * 32 + (lane & 15)) * AR_ST + (lane >> 4) * 8) * 2;
    const uint32_t bOff = (uint32_t)((wn * 64 + (lane >> 4) * 8 + (lane & 7)) * AS_STRIDE
                                     + ((lane >> 3) & 1) * 8) * 2;

    for (int ch = 0; ch < 4; ++ch) {
        if (ch + 1 < 4)
            load_tileB8(sb + AR_BYTES + (uint32_t)((ch + 1) & 1) * EB_BYTES, W2t, K,
                        (ch + 1) << 6, tid);
        CP_COMMIT();
        CP_WAIT1();
        __syncthreads();

        const uint32_t bufB = sb + AR_BYTES + (uint32_t)(ch & 1) * EB_BYTES;
        #pragma unroll
        for (int ks = 0; ks < 4; ++ks) {
            const uint32_t kbA = (uint32_t)(ch * 64 + ks * 16) * 2;
            const uint32_t kbB = (uint32_t)(ks * 16) * 2;
            uint32_t afr[2][4];
            #pragma unroll
            for (int mt = 0; mt < 2; ++mt)
                ldmx4(afr[mt], sb + aOff + (uint32_t)(mt * 16 * AR_ST) * 2 + kbA);
            uint32_t bfr[8][2];
            #pragma unroll
            for (int p = 0; p < 4; ++p) {
                uint32_t r[4];
                ldmx4(r, bufB + bOff + (uint32_t)(p * 16 * AS_STRIDE) * 2 + kbB);
                bfr[2 * p][0] = r[0]; bfr[2 * p][1] = r[1];
                bfr[2 * p + 1][0] = r[2]; bfr[2 * p + 1][1] = r[3];
            }
            #pragma unroll
            for (int mt = 0; mt < 2; ++mt)
                #pragma unroll
                for (int nt = 0; nt < 8; ++nt)
                    mma16(acc[mt][nt], afr[mt], bfr[nt]);
        }
        __syncthreads();
    }

    const int lg = lane >> 2;
    const int lt = lane & 3;
    #pragma unroll
    for (int mt = 0; mt < 2; ++mt) {
        #pragma unroll
        for (int nt = 0; nt < 8; ++nt) {
            const int gc = wn * 64 + nt * 8 + 2 * lt;
            const float b0 = b2[gc], b1v = b2[gc + 1];
            #pragma unroll
            for (int h = 0; h < 2; ++h) {
                const int gr = m0 + wm * 32 + mt * 16 + lg + 8 * h;
                if (gr >= M) continue;
                __nv_bfloat162 o;
                o.x = __float2bfloat16(fmaxf(acc[mt][nt][2 * h + 0] + b0, 0.0f));
                o.y = __float2bfloat16(fmaxf(acc[mt][nt][2 * h + 1] + b1v, 0.0f));
                *reinterpret_cast<__nv_bfloat162*>(Cout + (size_t)gr * 256 + gc) = o;
            }
        }
    }
}

// ===========================================================================
// Fused Wl3+Wl4: 64-row tiles, 2-stage, 2 CTAs/SM. Fast sigmoid epilogue.
// ===========================================================================
#define L3_STRIDE 136
#define F2_BUF ((64 + 128) * AS_STRIDE * 2)   // 27648
#define F2_PIPE (2 * F2_BUF)                  // 55296
#define L3BYTES (64 * L3_STRIDE * 2)          // 17408
#define W4BYTES (64 * L3_STRIDE * 2)          // 17408
#define FUSED_SMEM (F2_PIPE + L3BYTES + W4BYTES)  // 90112

__global__ __launch_bounds__(256, 2)
void tc_fused34(const __nv_bfloat16* __restrict__ A, const __nv_bfloat16* __restrict__ W3t,
                const __nv_bfloat16* __restrict__ W4t,
                const float* __restrict__ b3, const float* __restrict__ b4,
                float* __restrict__ out, int M) {
    extern __shared__ __align__(16) char smem[];
    const uint32_t sb = smem_u32(smem);
    const uint32_t l3b = sb + F2_PIPE;
    const uint32_t w4b = l3b + L3BYTES;
    const int tid = threadIdx.x;
    const int lane = tid & 31;
    const int wid = tid >> 5;
    const int wm = wid & 1;
    const int wn = wid >> 1;
    const int m0 = blockIdx.x * 64;

    #pragma unroll
    for (int i = 0; i < 4; ++i) {
        int idx = tid + 256 * i;
        int row = idx >> 4;
        int c8 = (idx & 15) * 8;
        CP_ASYNC16(w4b + (uint32_t)(row * L3_STRIDE + c8) * 2, W4t + row * 128 + c8);
    }
    CP_COMMIT();

    float acc[2][4][4];
    #pragma unroll
    for (int mt = 0; mt < 2; ++mt)
        #pragma unroll
        for (int nt = 0; nt < 4; ++nt)
            #pragma unroll
            for (int q = 0; q < 4; ++q) acc[mt][nt][q] = 0.0f;

    const uint32_t aOff = (uint32_t)((wm * 32 + (lane & 15)) * AS_STRIDE + (lane >> 4) * 8) * 2;
    const uint32_t bOff = (uint32_t)((wn * 32 + (lane >> 4) * 8 + (lane & 7)) * AS_STRIDE
                                     + ((lane >> 3) & 1) * 8) * 2;

    load_tileM<2>(sb, A, W3t, M, 256, 128, m0, 0, 0, tid);
    CP_COMMIT();
    for (int ch = 0; ch < 4; ++ch) {
        if (ch + 1 < 4)
            load_tileM<2>(sb + (uint32_t)((ch + 1) & 1) * F2_BUF, A, W3t, M, 256, 128,
                          m0, 0, (ch + 1) << 6, tid);
        CP_COMMIT();
        CP_WAIT1();
        __syncthreads();
        const uint32_t bufA = sb + (uint32_t)(ch & 1) * F2_BUF;
        const uint32_t bufB = bufA + 64 * AS_STRIDE * 2;
        #pragma unroll
        for (int ks = 0; ks < 4; ++ks) {
            const uint32_t kb = (uint32_t)(ks * 16) * 2;
            uint32_t afr[2][4];
            #pragma unroll
            for (int mt = 0; mt < 2; ++mt)
                ldmx4(afr[mt], bufA + aOff + (uint32_t)(mt * 16 * AS_STRIDE) * 2 + kb);
            uint32_t bfr[4][2];
            #pragma unroll
            for (int p = 0; p < 2; ++p) {
                uint32_t r[4];
                ldmx4(r, bufB + bOff + (uint32_t)(p * 16 * AS_STRIDE) * 2 + kb);
                bfr[2 * p][0] = r[0]; bfr[2 * p][1] = r[1];
                bfr[2 * p + 1][0] = r[2]; bfr[2 * p + 1][1] = r[3];
            }
            #pragma unroll
            for (int mt = 0; mt < 2; ++mt)
                #pragma unroll
                for (int nt = 0; nt < 4; ++nt)
                    mma16(acc[mt][nt], afr[mt], bfr[nt]);
        }
        __syncthreads();
    }

    const int lg = lane >> 2;
    const int lt = lane & 3;
    #pragma unroll
    for (int mt = 0; mt < 2; ++mt) {
        #pragma unroll
        for (int nt = 0; nt < 4; ++nt) {
            const int gc = wn * 32 + nt * 8 + 2 * lt;
            const float b0 = b3[gc], b1v = b3[gc + 1];
            #pragma unroll
            for (int h = 0; h < 2; ++h) {
                const int row = wm * 32 + mt * 16 + lg + 8 * h;
                __nv_bfloat162 o;
                o.x = __float2bfloat16(fmaxf(acc[mt][nt][2 * h + 0] + b0, 0.0f));
                o.y = __float2bfloat16(fmaxf(acc[mt][nt][2 * h + 1] + b1v, 0.0f));
                *reinterpret_cast<__nv_bfloat162*>(smem + F2_PIPE + (uint32_t)(row * L3_STRIDE + gc) * 2) = o;
            }
        }
    }
    CP_WAIT0();
    __syncthreads();

    float acc2[2][2][4];
    #pragma unroll
    for (int mt = 0; mt < 2; ++mt)
        #pragma unroll
        for (int nt = 0; nt < 2; ++nt)
            #pragma unroll
            for (int q = 0; q < 4; ++q) acc2[mt][nt][q] = 0.0f;

    const uint32_t aOff2 = (uint32_t)((wm * 32 + (lane & 15)) * L3_STRIDE + (lane >> 4) * 8) * 2;
    const uint32_t bOff2 = (uint32_t)((wn * 16 + (lane >> 4) * 8 + (lane & 7)) * L3_STRIDE
                                      + ((lane >> 3) & 1) * 8) * 2;
    #pragma unroll
    for (int ks = 0; ks < 8; ++ks) {
        const uint32_t kb = (uint32_t)(ks * 16) * 2;
        uint32_t afr[2][4];
        #pragma unroll
        for (int mt = 0; mt < 2; ++mt)
            ldmx4(afr[mt], l3b + aOff2 + (uint32_t)(mt * 16 * L3_STRIDE) * 2 + kb);
        uint32_t r[4];
        ldmx4(r, w4b + bOff2 + kb);
        uint32_t bfr[2][2] = {{r[0], r[1]}, {r[2], r[3]}};
        #pragma unroll
        for (int mt = 0; mt < 2; ++mt)
            #pragma unroll
            for (int nt = 0; nt < 2; ++nt)
                mma16(acc2[mt][nt], afr[mt], bfr[nt]);
    }

    #pragma unroll
    for (int mt = 0; mt < 2; ++mt) {
        #pragma unroll
        for (int nt = 0; nt < 2; ++nt) {
            const int gc = wn * 16 + nt * 8 + 2 * lt;
            const float b0 = b4[gc], b1v = b4[gc + 1];
            #pragma unroll
            for (int h = 0; h < 2; ++h) {
                const int gr = m0 + wm * 32 + mt * 16 + lg + 8 * h;
                if (gr >= M) continue;
                float v0 = fast_sigmoid(acc2[mt][nt][2 * h + 0] + b0);
                float v1 = fast_sigmoid(acc2[mt][nt][2 * h + 1] + b1v);
                *reinterpret_cast<float2*>(out + (size_t)gr * 64 + gc) = make_float2(v0, v1);
            }
        }
    }
}

// ---------------------------------------------------------------------------
// Launch
// ---------------------------------------------------------------------------
extern "C" void kernel_launch(void* const* d_in, const int* in_sizes, int n_in,
                              void* d_out, int out_size) {
    const float* x1  = (const float*)d_in[0];
    const float* x2  = (const float*)d_in[3];
    const float* W1  = (const float*)d_in[6];
    const float* b1  = (const float*)d_in[7];
    const float* W2  = (const float*)d_in[8];
    const float* b2  = (const float*)d_in[9];
    const float* W3  = (const float*)d_in[10];
    const float* b3  = (const float*)d_in[11];
    const float* Wl1 = (const float*)d_in[12];
    const float* bl1 = (const float*)d_in[13];
    const float* Wl2 = (const float*)d_in[14];
    const float* bl2 = (const float*)d_in[15];
    const float* Wl3 = (const float*)d_in[16];
    const float* bl3 = (const float*)d_in[17];
    const float* Wl4 = (const float*)d_in[18];
    const float* bl4 = (const float*)d_in[19];
    float* out = (float*)d_out;

    __nv_bfloat16 *bufA, *bufB, *bufC, *bufW;
    cudaGetSymbolAddress((void**)&bufA, g_bufA);
    cudaGetSymbolAddress((void**)&bufB, g_bufB);
    cudaGetSymbolAddress((void**)&bufC, g_bufC);
    cudaGetSymbolAddress((void**)&bufW, g_bufW);

    const int SM3 = NSTAGE * ((3 * 32 + 128) * AS_STRIDE * 2);   // 96768

    cudaFuncSetAttribute(tc_enc1, cudaFuncAttributeMaxDynamicSharedMemorySize, E1_SMEM);
    cudaFuncSetAttribute(tc_gemm<3, 1, false>, cudaFuncAttributeMaxDynamicSharedMemorySize, SM3);
    cudaFuncSetAttribute(tc_gemm<3, 1, true >, cudaFuncAttributeMaxDynamicSharedMemorySize, SM3);
    cudaFuncSetAttribute(tc_fused34, cudaFuncAttributeMaxDynamicSharedMemorySize, FUSED_SMEM);

    const int MT2R = (ROWS2 + 95) / 96;   // 261 (conv3 row tiles, 96 rows)
    const int MT1R = (NG + 95) / 96;      // 131 (head row tiles, 96 rows)

    // W2 conversion only (needed by enc1); rest folded into enc1's grid tail.
    cvt_w2<<<64, 256>>>(W2, bufW);

    // Encoder: layer1+conv2 fused (+ cvt tail for W3..Wl4), then conv3 (split-concat)
    tc_enc1<<<ENC_TILES + CVT_TAIL, 256, E1_SMEM>>>(x1, x2, W1, b1, bufW + OFF_W2, b2, bufB,
                                                    W3, Wl1, Wl2, Wl3, Wl4, bufW);
    tc_gemm<3, 1, true ><<<dim3(MT2R, 2), 256, SM3>>>(bufB, bufW + OFF_W3, b3, bufC, ROWS2, 256, 256, 512, NG);

    // Head
    tc_gemm<3, 1, false><<<dim3(MT1R, 4), 256, SM3>>>(bufC, bufW + OFF_WL1, bl1, bufA, NG, 512, 512, 512, 0);
    tc_gemm<3, 1, false><<<dim3(MT1R, 2), 256, SM3>>>(bufA, bufW + OFF_WL2, bl2, bufB, NG, 512, 256, 256, 0);
    tc_fused34<<<(NG + 63) / 64, 256, FUSED_SMEM>>>(bufB, bufW + OFF_WL3, bufW + OFF_WL4, bl3, bl4, out, NG);
}